// round 10
// baseline (speedup 1.0000x reference)
#include <cuda_runtime.h>
#include <math.h>

#define LEVEL 16
#define NBLK_R 2048           // reduce blocks (also partials count)
#define TPB_R 128             // reduce block size (small CTAs -> phase desync)
#define TPB_S 128             // scan block size

// Per-block partial sums from the reduce pass. Every slot is overwritten
// deterministically on every launch — no init kernel, no atomics.
__device__ double g_partials[NBLK_R];

// ---------------------------------------------------------------------------
// Pass 1: partials[b] = sum over this block's j of | sum_t x[t, j] |
// Grid-stride forward. Cache-hint split: all iterations except the LAST use
// __ldcs (evict-first — the scan reads that data last, it can never survive
// in L2 anyway), the last iteration uses __ldcg so the top-j quarter is the
// protected L2 residue the reverse-order scan consumes first.
// ---------------------------------------------------------------------------
__global__ void __launch_bounds__(TPB_R) reduce_kernel(const float4* __restrict__ x, int M4) {
    int tid = blockIdx.x * blockDim.x + threadIdx.x;
    int stride = gridDim.x * blockDim.x;

    float acc = 0.0f;
    for (int j = tid; j < M4; j += stride) {
        bool last_iter = (j + stride >= M4);      // final grid-stride pass
        float sx = 0.f, sy = 0.f, sz = 0.f, sw = 0.f;
        if (last_iter) {
#pragma unroll
            for (int t = 0; t < LEVEL; t++) {
                float4 v = __ldcg(&x[(size_t)t * M4 + j]);
                sx += v.x; sy += v.y; sz += v.z; sw += v.w;
            }
        } else {
#pragma unroll
            for (int t = 0; t < LEVEL; t++) {
                float4 v = __ldcs(&x[(size_t)t * M4 + j]);
                sx += v.x; sy += v.y; sz += v.z; sw += v.w;
            }
        }
        acc += fabsf(sx) + fabsf(sy) + fabsf(sz) + fabsf(sw);
    }

#pragma unroll
    for (int o = 16; o > 0; o >>= 1)
        acc += __shfl_down_sync(0xFFFFFFFFu, acc, o);

    __shared__ float warp_sums[TPB_R / 32];
    int lane = threadIdx.x & 31;
    int wid  = threadIdx.x >> 5;
    if (lane == 0) warp_sums[wid] = acc;
    __syncthreads();

    if (wid == 0) {
        acc = (lane < TPB_R / 32) ? warp_sums[lane] : 0.0f;
#pragma unroll
        for (int o = 16; o > 0; o >>= 1)
            acc += __shfl_down_sync(0xFFFFFFFFu, acc, o);
        if (lane == 0) g_partials[blockIdx.x] = (double)acc;
    }
}

// One ST-BIF neuron step (matches reference: neg overrides pos).
__device__ __forceinline__ float bif_step(float& v, float& T, float xt, float v_th) {
    v += xt;
    float s = 0.0f;
    if (v - v_th >= 0.0f && T - 15.0f < 0.0f) s = 1.0f;
    if (v < 0.0f && T > 0.0f)                 s = -1.0f;
    v -= v_th * s;
    T += s;
    return s;
}

// ---------------------------------------------------------------------------
// Pass 2: per-column 16-step scan. Preamble first (regs ~80, occ 33%), then
// ALL 16 loads batched (MLP=16). Reverse j order: first waves consume the
// protected top-j L2 residue from pass 1. __ldcs/__stcs keep this pass's
// traffic evict-first.
// ---------------------------------------------------------------------------
__global__ void __launch_bounds__(TPB_S) scan_kernel(const float4* __restrict__ x,
                                                     float4* __restrict__ out, int M4) {
    // Preamble: warp 0 sums the 2048 partials (16 KB, L2-hot), computes v_th.
    __shared__ float s_vth;
    if (threadIdx.x < 32) {
        double d = 0.0;
#pragma unroll 4
        for (int i = threadIdx.x; i < NBLK_R; i += 32)
            d += g_partials[i];
#pragma unroll
        for (int o = 16; o > 0; o >>= 1)
            d += __shfl_down_sync(0xFFFFFFFFu, d, o);
        if (threadIdx.x == 0) {
            double mean = d / (4.0 * (double)M4);
            s_vth = (float)(mean * 2.0 / sqrt(15.0));
        }
    }
    __syncthreads();
    float v_th = s_vth;

    // Reverse block mapping: block 0 handles the highest j range.
    int jblk = gridDim.x - 1 - blockIdx.x;
    int j = jblk * TPB_S + threadIdx.x;
    if (j >= M4) return;

    // Burst-read all 16 time steps (64 data regs in flight, MLP=16).
    float4 r[LEVEL];
#pragma unroll
    for (int t = 0; t < LEVEL; t++)
        r[t] = __ldcs(&x[(size_t)t * M4 + j]);

    float vx = 0.5f * v_th, vy = vx, vz = vx, vw = vx;
    float Tx = 0.f, Ty = 0.f, Tz = 0.f, Tw = 0.f;

#pragma unroll
    for (int t = 0; t < LEVEL; t++) {
        float4 o;
        o.x = bif_step(vx, Tx, r[t].x, v_th) * v_th;
        o.y = bif_step(vy, Ty, r[t].y, v_th) * v_th;
        o.z = bif_step(vz, Tz, r[t].z, v_th) * v_th;
        o.w = bif_step(vw, Tw, r[t].w, v_th) * v_th;
        __stcs(&out[(size_t)t * M4 + j], o);
    }
}

extern "C" void kernel_launch(void* const* d_in, const int* in_sizes, int n_in,
                              void* d_out, int out_size) {
    const float4* x = (const float4*)d_in[0];
    float4* out = (float4*)d_out;

    int n_total = in_sizes[0];         // 32*2048*1024
    int M4 = n_total / LEVEL / 4;      // 1,048,576 float4 columns

    reduce_kernel<<<NBLK_R, TPB_R>>>(x, M4);
    scan_kernel<<<(M4 + TPB_S - 1) / TPB_S, TPB_S>>>(x, out, M4);
}

// round 11
// speedup vs baseline: 1.0123x; 1.0123x over previous
#include <cuda_runtime.h>
#include <math.h>

#define LEVEL 16
#define NBLK_R 1024           // reduce blocks (also partials count)
#define TPB_R 256             // reduce block size
#define TPB_S 128             // scan block size
#define MAXG_S 2048

// Per-block partial sums from the reduce pass. Every slot is overwritten
// deterministically on every launch — no init kernel, no atomics.
__device__ double g_partials[NBLK_R];

// ---------------------------------------------------------------------------
// Pass 1 (champion config): partials[b] = sum_j | sum_t x[t, j] | per block.
// Forward grid-stride + __ldcg: tail of input stays L2-resident for pass 2.
// ---------------------------------------------------------------------------
__global__ void reduce_kernel(const float4* __restrict__ x, int M4) {
    int tid = blockIdx.x * blockDim.x + threadIdx.x;
    int stride = gridDim.x * blockDim.x;

    float acc = 0.0f;
    for (int j = tid; j < M4; j += stride) {
        float sx = 0.f, sy = 0.f, sz = 0.f, sw = 0.f;
#pragma unroll
        for (int t = 0; t < LEVEL; t++) {
            float4 v = __ldcg(&x[(size_t)t * M4 + j]);
            sx += v.x; sy += v.y; sz += v.z; sw += v.w;
        }
        acc += fabsf(sx) + fabsf(sy) + fabsf(sz) + fabsf(sw);
    }

#pragma unroll
    for (int o = 16; o > 0; o >>= 1)
        acc += __shfl_down_sync(0xFFFFFFFFu, acc, o);

    __shared__ float warp_sums[TPB_R / 32];
    int lane = threadIdx.x & 31;
    int wid  = threadIdx.x >> 5;
    if (lane == 0) warp_sums[wid] = acc;
    __syncthreads();

    if (wid == 0) {
        acc = (lane < TPB_R / 32) ? warp_sums[lane] : 0.0f;
#pragma unroll
        for (int o = 16; o > 0; o >>= 1)
            acc += __shfl_down_sync(0xFFFFFFFFu, acc, o);
        if (lane == 0) g_partials[blockIdx.x] = (double)acc;
    }
}

// One ST-BIF step returning a 2-bit spike code: 0 -> 0, 1 -> +1, 2 -> -1.
// Matches reference semantics (neg overrides pos).
__device__ __forceinline__ int bif_step_code(float& v, float& T, float xt, float v_th) {
    v += xt;
    int code = 0;
    if (v - v_th >= 0.0f && T - 15.0f < 0.0f) code = 1;
    if (v < 0.0f && T > 0.0f)                 code = 2;
    float s = (code == 1) ? 1.0f : ((code == 2) ? -1.0f : 0.0f);
    v -= v_th * s;
    T += s;
    return code;
}

__device__ __forceinline__ float decode_spike(unsigned c, float v_th) {
    return (c == 1u) ? v_th : ((c == 2u) ? -v_th : 0.0f);
}

// ---------------------------------------------------------------------------
// Pass 2: persistent scan with deferred packed stores.
// Per batch: compute spikes from register buffer -> pack into 4 u32;
// ISSUE next batch's 16 loads; then unpack+store this batch's 16 planes
// while the loads are in flight. Reads and writes overlap continuously.
// Batches iterate in REVERSE j order (L2 residue from pass 1 hit first).
// ---------------------------------------------------------------------------
__global__ void __launch_bounds__(TPB_S) scan_kernel(const float4* __restrict__ x,
                                                     float4* __restrict__ out, int M4) {
    // Preamble: warp 0 sums the 1024 partials (8 KB, L2-hot), computes v_th.
    __shared__ float s_vth;
    if (threadIdx.x < 32) {
        double d = 0.0;
#pragma unroll
        for (int i = threadIdx.x; i < NBLK_R; i += 32)
            d += g_partials[i];
#pragma unroll
        for (int o = 16; o > 0; o >>= 1)
            d += __shfl_down_sync(0xFFFFFFFFu, d, o);
        if (threadIdx.x == 0) {
            double mean = d / (4.0 * (double)M4);
            s_vth = (float)(mean * 2.0 / sqrt(15.0));
        }
    }
    __syncthreads();
    const float v_th = s_vth;

    const int P = gridDim.x * TPB_S;
    const int p = blockIdx.x * TPB_S + threadIdx.x;
    const int B = (M4 + P - 1) / P;              // batches per thread

    float4 r[LEVEL];

    // Prologue: load top batch (only batch that can be partially invalid).
    const int jtop = (B - 1) * P + p;
    const bool vtop = (jtop < M4);
    if (vtop) {
#pragma unroll
        for (int t = 0; t < LEVEL; t++)
            r[t] = __ldcs(&x[(size_t)t * M4 + jtop]);
    }

    for (int b = B - 1; b >= 0; b--) {
        const int j = b * P + p;
        const bool valid = (b < B - 1) || vtop;

        // 1) Compute + pack spikes for batch b (frees the load buffer r).
        unsigned pk[4] = {0u, 0u, 0u, 0u};
        if (valid) {
            float vx = 0.5f * v_th, vy = vx, vz = vx, vw = vx;
            float Tx = 0.f, Ty = 0.f, Tz = 0.f, Tw = 0.f;
#pragma unroll
            for (int t = 0; t < LEVEL; t++) {
                unsigned byte =
                    (unsigned)bif_step_code(vx, Tx, r[t].x, v_th)
                  | ((unsigned)bif_step_code(vy, Ty, r[t].y, v_th) << 2)
                  | ((unsigned)bif_step_code(vz, Tz, r[t].z, v_th) << 4)
                  | ((unsigned)bif_step_code(vw, Tw, r[t].w, v_th) << 6);
                pk[t >> 2] |= byte << ((t & 3) * 8);
            }
        }

        // 2) Issue next batch's loads (b-1 < B-1 is always fully valid).
        if (b > 0) {
            const int jn = (b - 1) * P + p;
#pragma unroll
            for (int t = 0; t < LEVEL; t++)
                r[t] = __ldcs(&x[(size_t)t * M4 + jn]);
        }

        // 3) Store batch b's outputs while the loads are in flight.
        if (valid) {
#pragma unroll
            for (int t = 0; t < LEVEL; t++) {
                unsigned byte = pk[t >> 2] >> ((t & 3) * 8);
                float4 o;
                o.x = decode_spike( byte        & 3u, v_th);
                o.y = decode_spike((byte >> 2)  & 3u, v_th);
                o.z = decode_spike((byte >> 4)  & 3u, v_th);
                o.w = decode_spike((byte >> 6)  & 3u, v_th);
                __stcs(&out[(size_t)t * M4 + j], o);
            }
        }
    }
}

extern "C" void kernel_launch(void* const* d_in, const int* in_sizes, int n_in,
                              void* d_out, int out_size) {
    const float4* x = (const float4*)d_in[0];
    float4* out = (float4*)d_out;

    int n_total = in_sizes[0];         // 32*2048*1024
    int M4 = n_total / LEVEL / 4;      // 1,048,576 float4 columns

    reduce_kernel<<<NBLK_R, TPB_R>>>(x, M4);

    // Persistent scan grid: SMs x resident CTAs (batches are independent,
    // no inter-CTA sync, so any grid size is correct).
    int dev = 0;
    cudaGetDevice(&dev);
    int sms = 0;
    cudaDeviceGetAttribute(&sms, cudaDevAttrMultiProcessorCount, dev);
    int nb = 0;
    cudaOccupancyMaxActiveBlocksPerMultiprocessor(&nb, scan_kernel, TPB_S, 0);
    if (nb < 1) nb = 1;
    long long G = (long long)sms * nb;
    if (G > MAXG_S) G = MAXG_S;

    scan_kernel<<<(int)G, TPB_S>>>(x, out, M4);
}

// round 12
// speedup vs baseline: 1.0741x; 1.0610x over previous
#include <cuda_runtime.h>
#include <math.h>

#define LEVEL 16
#define NBLK_R 1024           // reduce blocks (also partials count)
#define TPB_R 256             // reduce block size
#define TPB_S 128             // scan block size

// Per-block partial sums from the reduce pass. Every slot is overwritten
// deterministically on every launch — no init kernel, no atomics.
__device__ double g_partials[NBLK_R];

// ---------------------------------------------------------------------------
// Pass 1: partials[b] = sum over this block's j of | sum_t x[t, j] |
// Forward grid-stride + __ldcg: tail of input stays L2-resident for pass 2.
// Triggers the dependent scan launch as soon as its partial is visible
// (PDL), overlapping the scan's launch/preamble with this grid's drain.
// ---------------------------------------------------------------------------
__global__ void reduce_kernel(const float4* __restrict__ x, int M4) {
    int tid = blockIdx.x * blockDim.x + threadIdx.x;
    int stride = gridDim.x * blockDim.x;

    float acc = 0.0f;
    for (int j = tid; j < M4; j += stride) {
        float sx = 0.f, sy = 0.f, sz = 0.f, sw = 0.f;
#pragma unroll
        for (int t = 0; t < LEVEL; t++) {
            float4 v = __ldcg(&x[(size_t)t * M4 + j]);
            sx += v.x; sy += v.y; sz += v.z; sw += v.w;
        }
        acc += fabsf(sx) + fabsf(sy) + fabsf(sz) + fabsf(sw);
    }

#pragma unroll
    for (int o = 16; o > 0; o >>= 1)
        acc += __shfl_down_sync(0xFFFFFFFFu, acc, o);

    __shared__ float warp_sums[TPB_R / 32];
    int lane = threadIdx.x & 31;
    int wid  = threadIdx.x >> 5;
    if (lane == 0) warp_sums[wid] = acc;
    __syncthreads();

    if (wid == 0) {
        acc = (lane < TPB_R / 32) ? warp_sums[lane] : 0.0f;
#pragma unroll
        for (int o = 16; o > 0; o >>= 1)
            acc += __shfl_down_sync(0xFFFFFFFFu, acc, o);
        if (lane == 0) {
            g_partials[blockIdx.x] = (double)acc;
            __threadfence();                 // partial visible device-wide
        }
    }
    __syncthreads();
    // Fire PDL trigger: dependent grid may launch once ALL CTAs have
    // executed this (i.e., all partials written + fenced).
    cudaTriggerProgrammaticLaunchCompletion();
}

// One ST-BIF neuron step (matches reference: neg overrides pos).
__device__ __forceinline__ float bif_step(float& v, float& T, float xt, float v_th) {
    v += xt;
    float s = 0.0f;
    if (v - v_th >= 0.0f && T - 15.0f < 0.0f) s = 1.0f;
    if (v < 0.0f && T > 0.0f)                 s = -1.0f;
    v -= v_th * s;
    T += s;
    return s;
}

// ---------------------------------------------------------------------------
// Pass 2: per-column 16-step scan (champion config). Waits on the PDL
// dependency, then preamble (v_th), then the 16-load burst (MLP=16).
// Reverse j order hits the L2 residue from pass 1.
// ---------------------------------------------------------------------------
__global__ void __launch_bounds__(TPB_S) scan_kernel(const float4* __restrict__ x,
                                                     float4* __restrict__ out, int M4) {
    // Wait for the upstream grid's trigger (all partials visible).
    cudaGridDependencySynchronize();

    // Preamble: warp 0 sums the 1024 partials (8 KB, L2-hot), computes v_th.
    __shared__ float s_vth;
    if (threadIdx.x < 32) {
        double d = 0.0;
#pragma unroll
        for (int i = threadIdx.x; i < NBLK_R; i += 32)
            d += g_partials[i];
#pragma unroll
        for (int o = 16; o > 0; o >>= 1)
            d += __shfl_down_sync(0xFFFFFFFFu, d, o);
        if (threadIdx.x == 0) {
            double mean = d / (4.0 * (double)M4);
            s_vth = (float)(mean * 2.0 / sqrt(15.0));
        }
    }
    __syncthreads();
    float v_th = s_vth;

    // Reverse block mapping: block 0 handles the highest j range.
    int jblk = gridDim.x - 1 - blockIdx.x;
    int j = jblk * TPB_S + threadIdx.x;
    if (j >= M4) return;

    // Burst-read all 16 time steps (64 data regs in flight, MLP=16).
    float4 r[LEVEL];
#pragma unroll
    for (int t = 0; t < LEVEL; t++)
        r[t] = __ldcs(&x[(size_t)t * M4 + j]);

    float vx = 0.5f * v_th, vy = vx, vz = vx, vw = vx;
    float Tx = 0.f, Ty = 0.f, Tz = 0.f, Tw = 0.f;

#pragma unroll
    for (int t = 0; t < LEVEL; t++) {
        float4 o;
        o.x = bif_step(vx, Tx, r[t].x, v_th) * v_th;
        o.y = bif_step(vy, Ty, r[t].y, v_th) * v_th;
        o.z = bif_step(vz, Tz, r[t].z, v_th) * v_th;
        o.w = bif_step(vw, Tw, r[t].w, v_th) * v_th;
        __stcs(&out[(size_t)t * M4 + j], o);
    }
}

extern "C" void kernel_launch(void* const* d_in, const int* in_sizes, int n_in,
                              void* d_out, int out_size) {
    const float4* x = (const float4*)d_in[0];
    float4* out = (float4*)d_out;

    int n_total = in_sizes[0];         // 32*2048*1024
    int M4 = n_total / LEVEL / 4;      // 1,048,576 float4 columns

    reduce_kernel<<<NBLK_R, TPB_R>>>(x, M4);

    // Scan launched with PDL: may begin while the reduce grid drains.
    cudaLaunchAttribute attrs[1];
    attrs[0].id = cudaLaunchAttributeProgrammaticStreamSerialization;
    attrs[0].val.programmaticStreamSerializationAllowed = 1;

    cudaLaunchConfig_t cfg = {};
    cfg.gridDim  = dim3((M4 + TPB_S - 1) / TPB_S);
    cfg.blockDim = dim3(TPB_S);
    cfg.dynamicSmemBytes = 0;
    cfg.stream = 0;                    // same (capture) stream as reduce
    cfg.attrs = attrs;
    cfg.numAttrs = 1;

    cudaLaunchKernelEx(&cfg, scan_kernel, x, out, M4);
}

// round 13
// speedup vs baseline: 1.0952x; 1.0197x over previous
#include <cuda_runtime.h>
#include <math.h>

#define LEVEL 16
#define TPB 128
#define MAXG 2048

// All counters MONOTONIC (never reset) -> deterministic under graph replay:
// per launch, g_t1 and g_t2 each advance by exactly NB+G (every CTA's last
// grab fails exactly once), g_arrive by exactly G. Epochs are recovered by
// modulo, so no per-launch reset is needed.
__device__ double             g_partials[MAXG];
__device__ unsigned long long g_t1;       // phase-1 batch tickets
__device__ unsigned long long g_t2;       // phase-2 batch tickets
__device__ unsigned long long g_arrive;   // barrier arrivals

// One ST-BIF neuron step (matches reference: neg overrides pos).
__device__ __forceinline__ float bif_step(float& v, float& T, float xt, float v_th) {
    v += xt;
    float s = 0.0f;
    if (v - v_th >= 0.0f && T - 15.0f < 0.0f) s = 1.0f;
    if (v < 0.0f && T > 0.0f)                 s = -1.0f;
    v -= v_th * s;
    T += s;
    return s;
}

__device__ __forceinline__ void scan_batch(const float4* r, float4* __restrict__ out,
                                           int j, int M4, float v_th) {
    float vx = 0.5f * v_th, vy = vx, vz = vx, vw = vx;
    float Tx = 0.f, Ty = 0.f, Tz = 0.f, Tw = 0.f;
#pragma unroll
    for (int t = 0; t < LEVEL; t++) {
        float4 o;
        o.x = bif_step(vx, Tx, r[t].x, v_th) * v_th;
        o.y = bif_step(vy, Ty, r[t].y, v_th) * v_th;
        o.z = bif_step(vz, Tz, r[t].z, v_th) * v_th;
        o.w = bif_step(vw, Tw, r[t].w, v_th) * v_th;
        __stcs(&out[(size_t)t * M4 + j], o);
    }
}

// CTA-collective ticket grab: returns launch-local ticket index in [0, NB+G).
__device__ __forceinline__ int grab(unsigned long long* ctr, unsigned long long NBG,
                                    volatile unsigned long long* s_tick) {
    if (threadIdx.x == 0) *s_tick = atomicAdd(ctr, 1ULL);
    __syncthreads();
    int k = (int)(*s_tick % NBG);
    __syncthreads();          // everyone has read before the next overwrite
    return k;
}

// ---------------------------------------------------------------------------
// Single-wave persistent fused kernel with WORK-STEALING in both phases:
// no static partition -> no straggler tail at the grid barrier.
// Phase 1: steal batches (ascending ticket order ~ ascending j), reduce.
// Barrier (epoch on g_arrive), first phase-2 batch's loads issued BEFORE the
// spin. Phase 2: steal batches mapped in REVERSE j (hits L2 residue hottest-
// first), 16-load burst -> scan -> 16 stores per batch.
// ---------------------------------------------------------------------------
__global__ void __launch_bounds__(TPB) fused_kernel(const float4* __restrict__ x,
                                                    float4* __restrict__ out, int M4) {
    const int G  = gridDim.x;
    const int NB = (M4 + TPB - 1) / TPB;              // batches (CTA-sized)
    const unsigned long long NBG = (unsigned long long)NB + (unsigned long long)G;
    const int tid = threadIdx.x;
    const int lane = tid & 31, wid = tid >> 5;

    __shared__ unsigned long long s_tick;
    __shared__ unsigned long long s_target;
    __shared__ float wsum[TPB / 32];
    __shared__ float s_vth;

    // ---- Phase 1: work-stealing reduction ----
    float acc = 0.0f;
    for (;;) {
        int k = grab(&g_t1, NBG, &s_tick);
        if (k >= NB) break;
        int j = k * TPB + tid;
        if (j < M4) {
            float sx = 0.f, sy = 0.f, sz = 0.f, sw = 0.f;
#pragma unroll
            for (int t = 0; t < LEVEL; t++) {
                float4 v = __ldcg(&x[(size_t)t * M4 + j]);
                sx += v.x; sy += v.y; sz += v.z; sw += v.w;
            }
            acc += fabsf(sx) + fabsf(sy) + fabsf(sz) + fabsf(sw);
        }
    }

    // ---- CTA reduce -> partial, arrive on barrier ----
#pragma unroll
    for (int o = 16; o > 0; o >>= 1)
        acc += __shfl_down_sync(0xFFFFFFFFu, acc, o);
    if (lane == 0) wsum[wid] = acc;
    __syncthreads();
    if (tid == 0) {
        float a = 0.f;
#pragma unroll
        for (int i = 0; i < TPB / 32; i++) a += wsum[i];
        g_partials[blockIdx.x] = (double)a;
        __threadfence();
        unsigned long long old = atomicAdd(&g_arrive, 1ULL);
        s_target = (old / (unsigned long long)G + 1ULL) * (unsigned long long)G;
    }
    __syncthreads();
    const unsigned long long target = s_target;

    // ---- Pre-grab first phase-2 batch, ISSUE its loads before the spin ----
    int k2 = grab(&g_t2, NBG, &s_tick);
    bool have = (k2 < NB);
    int j2 = (NB - 1 - k2) * TPB + tid;               // reverse j mapping
    bool val = have && (j2 < M4);
    float4 r[LEVEL];
    if (val) {
#pragma unroll
        for (int t = 0; t < LEVEL; t++)
            r[t] = __ldcs(&x[(size_t)t * M4 + j2]);
    }

    // ---- Barrier spin + decentralized v_th (loads in flight) ----
    if (tid < 32) {
        if (lane == 0) {
            while (atomicAdd(&g_arrive, 0ULL) < target) __nanosleep(64);
        }
        __syncwarp();
        __threadfence();
        double d = 0.0;
        for (int i = lane; i < G; i += 32)
            d += g_partials[i];
#pragma unroll
        for (int o = 16; o > 0; o >>= 1)
            d += __shfl_down_sync(0xFFFFFFFFu, d, o);
        if (lane == 0) {
            double mean = d / (4.0 * (double)M4);
            s_vth = (float)(mean * 2.0 / sqrt(15.0));
        }
    }
    __syncthreads();
    const float v_th = s_vth;

    // ---- Phase 2: work-stealing scan ----
    while (have) {
        if (val) scan_batch(r, out, j2, M4, v_th);
        k2 = grab(&g_t2, NBG, &s_tick);
        have = (k2 < NB);
        j2 = (NB - 1 - k2) * TPB + tid;
        val = have && (j2 < M4);
        if (val) {
#pragma unroll
            for (int t = 0; t < LEVEL; t++)
                r[t] = __ldcs(&x[(size_t)t * M4 + j2]);
        }
    }
}

extern "C" void kernel_launch(void* const* d_in, const int* in_sizes, int n_in,
                              void* d_out, int out_size) {
    const float4* x = (const float4*)d_in[0];
    float4* out = (float4*)d_out;

    int n_total = in_sizes[0];         // 32*2048*1024
    int M4 = n_total / LEVEL / 4;      // 1,048,576 float4 columns

    // Single-wave grid: co-residency guaranteed -> spin-barrier is safe.
    int dev = 0;
    cudaGetDevice(&dev);
    int sms = 0;
    cudaDeviceGetAttribute(&sms, cudaDevAttrMultiProcessorCount, dev);
    int nb = 0;
    cudaOccupancyMaxActiveBlocksPerMultiprocessor(&nb, fused_kernel, TPB, 0);
    if (nb < 1) nb = 1;
    long long G = (long long)sms * nb;
    if (G > MAXG) G = MAXG;

    fused_kernel<<<(int)G, TPB>>>(x, out, M4);
}